// round 4
// baseline (speedup 1.0000x reference)
#include <cuda_runtime.h>
#include <cstdint>

#define B_    32
#define T_    1024
#define N_    1024
#define D_    256
#define WIN_  100
#define TT_   32           // query-tile per block
#define NTHREADS 256

#define KST 132            // kbuf row stride (floats)
#define QROW 132           // qsT row stride: 32 t * 4 + 4 pad
#define PST 33             // prT row stride: [j][t]

#define KBUF_F (100*KST)           // 13200
#define QST_F  (64*QROW)           // 8448
#define PRT_F  (128*PST)           // 4224
#define SMEM_FLOATS (KBUF_F + QST_F + PRT_F)   // 25872
#define SMEM_BYTES  (SMEM_FLOATS * 4)          // 103488 B -> 2 CTAs/SM

typedef unsigned long long ull;

__device__ __forceinline__ void fma2(ull& acc, ull a, ull b) {
    asm("fma.rn.f32x2 %0, %1, %2, %0;" : "+l"(acc) : "l"(a), "l"(b));
}
__device__ __forceinline__ ull pack2(float lo, float hi) {
    ull r; asm("mov.b64 %0, {%1, %2};" : "=l"(r) : "f"(lo), "f"(hi)); return r;
}
__device__ __forceinline__ float lo2(ull v) {
    float a, b; asm("mov.b64 {%0, %1}, %2;" : "=f"(a), "=f"(b) : "l"(v)); return a;
}
__device__ __forceinline__ float hi2(ull v) {
    float a, b; asm("mov.b64 {%0, %1}, %2;" : "=f"(a), "=f"(b) : "l"(v)); return b;
}

// load 100 rows x 128 floats (d-half h) of row-major [N][256] window into dst[j*KST + d']
__device__ __forceinline__ void load_half(float* dst, const float* src, int h, int tid) {
    #pragma unroll
    for (int i = 0; i < 13; i++) {
        int idx = tid + NTHREADS * i;            // over 100*32 float4
        if (idx < 100*32) {
            int j = idx >> 5, c = idx & 31;
            float4 v = *(const float4*)(src + (size_t)j*D_ + 128*h + 4*c);
            *(float4*)(dst + j*KST + 4*c) = v;
        }
    }
}

__global__ __launch_bounds__(NTHREADS, 2)
void attn_main(const float* __restrict__ Q, const float* __restrict__ K,
               const float* __restrict__ V, const int* __restrict__ prev_arr,
               float* __restrict__ out_res, float* __restrict__ out_align,
               float* __restrict__ out_max)
{
    extern __shared__ float sm[];
    float* kbuf = sm;                  // [100][KST]  K half, later V half
    float* qsT  = sm + KBUF_F;         // [64 d4][t*4+c], 32 t
    float* prT  = qsT + QST_F;         // [128 j][PST]

    const int b    = blockIdx.y;
    const int t0   = blockIdx.x * TT_;
    const int tid  = threadIdx.x;
    const int warp = tid >> 5;         // 0..7
    const int lane = tid & 31;
    const int prev = prev_arr[b];

    const float* Qb = Q + ((size_t)b*T_ + t0) * D_;
    const float* Kw = K + ((size_t)b*N_ + prev) * D_;
    const float* Vw = V + ((size_t)b*N_ + prev) * D_;

    // ---- Load Q tile into qsT[d4][t*4+c] (32 t x 256 d) ----
    #pragma unroll
    for (int i = 0; i < 8; i++) {
        int idx = tid + NTHREADS * i;            // 32*64 float4
        int t = idx >> 6, c = idx & 63;
        float4 q = ((const float4*)Qb)[idx];
        *(float4*)(qsT + c*QROW + t*4) = q;
    }
    load_half(kbuf, Kw, 0, tid);
    __syncthreads();

    // ================= QK: warp owns j in [16w, 16w+16), lane owns t=lane ===========
    const int jw = warp * 16;
    ull acc2[16];
    #pragma unroll
    for (int i = 0; i < 16; i++) acc2[i] = 0ull;

    #pragma unroll 1
    for (int pass = 0; pass < 2; pass++) {
        #pragma unroll 2
        for (int d4 = 0; d4 < 32; d4++) {
            ulonglong2 q2 = *(const ulonglong2*)(qsT + (32*pass + d4)*QROW + 4*lane);
            #pragma unroll
            for (int i = 0; i < 16; i++) {
                ulonglong2 k2 = *(const ulonglong2*)(kbuf + (jw + i)*KST + 4*d4);
                fma2(acc2[i], q2.x, k2.x);
                fma2(acc2[i], q2.y, k2.y);
            }
        }
        if (pass == 0) {
            __syncthreads();
            load_half(kbuf, Kw, 1, tid);
            __syncthreads();
        }
    }
    const float scale = 0.0625f;
    #pragma unroll
    for (int i = 0; i < 16; i++)
        prT[(jw + i)*PST + lane] = (lo2(acc2[i]) + hi2(acc2[i])) * scale;
    __syncthreads();

    // ---- kbuf free: start V half-0 load now; latency hides under softmax ----
    load_half(kbuf, Vw, 0, tid);

    // ================= Softmax + argmax: warp owns rows t in [4w, 4w+4) =============
    const int trow = warp * 4;
    #pragma unroll
    for (int tt = 0; tt < 4; tt++) {
        int t = trow + tt;
        float v_[4];
        #pragma unroll
        for (int i = 0; i < 4; i++) v_[i] = prT[(lane + 32*i)*PST + t];   // conflict-free

        float mx = -3.4e38f;
        #pragma unroll
        for (int i = 0; i < 4; i++)
            if (lane + 32*i < WIN_) mx = fmaxf(mx, v_[i]);
        #pragma unroll
        for (int off = 16; off; off >>= 1)
            mx = fmaxf(mx, __shfl_xor_sync(0xffffffffu, mx, off));

        float e_[4]; float s = 0.f;
        #pragma unroll
        for (int i = 0; i < 4; i++) {
            e_[i] = (lane + 32*i < WIN_) ? __expf(v_[i] - mx) : 0.f;
            s += e_[i];
        }
        #pragma unroll
        for (int off = 16; off; off >>= 1)
            s += __shfl_xor_sync(0xffffffffu, s, off);
        float inv = 1.f / s;

        float pr[4];
        #pragma unroll
        for (int i = 0; i < 4; i++) pr[i] = e_[i] * inv;

        // first-occurrence argmax over final probs (jnp.argmax tie rule)
        float bm = -1.f; int bi = N_;
        #pragma unroll
        for (int i = 0; i < 4; i++)
            if (pr[i] > bm) { bm = pr[i]; bi = lane + 32*i; }
        #pragma unroll
        for (int off = 16; off; off >>= 1) {
            float om = __shfl_xor_sync(0xffffffffu, bm, off);
            int   oi = __shfl_xor_sync(0xffffffffu, bi, off);
            if (om > bm || (om == bm && oi < bi)) { bm = om; bi = oi; }
        }
        if (lane == 0)
            out_max[(size_t)b*T_ + t0 + t] = (float)(prev + bi);

        #pragma unroll
        for (int i = 0; i < 4; i++) prT[(lane + 32*i)*PST + t] = pr[i];
    }
    __syncthreads();   // probs final, V half-0 loaded

    // ================= PV pass loop: warp owns d-chunk [16w, 16w+16) of half ========
    const int dw = warp * 16;
    #pragma unroll 1
    for (int pass = 0; pass < 2; pass++) {
        ull pv[8];
        #pragma unroll
        for (int i = 0; i < 8; i++) pv[i] = 0ull;

        #pragma unroll 2
        for (int j = 0; j < WIN_; j++) {
            float pb = prT[j*PST + lane];
            ull pp = pack2(pb, pb);
            const float* vr = kbuf + j*KST + dw;
            ulonglong2 v0 = *(const ulonglong2*)(vr);
            ulonglong2 v1 = *(const ulonglong2*)(vr + 4);
            ulonglong2 v2 = *(const ulonglong2*)(vr + 8);
            ulonglong2 v3 = *(const ulonglong2*)(vr + 12);
            fma2(pv[0], pp, v0.x); fma2(pv[1], pp, v0.y);
            fma2(pv[2], pp, v1.x); fma2(pv[3], pp, v1.y);
            fma2(pv[4], pp, v2.x); fma2(pv[5], pp, v2.y);
            fma2(pv[6], pp, v3.x); fma2(pv[7], pp, v3.y);
        }
        // store 16 floats of out_res row (b, t0+lane), global d = 128*pass + dw
        float* dst = out_res + ((size_t)b*T_ + t0 + lane)*(2*D_) + 128*pass + dw;
        #pragma unroll
        for (int c = 0; c < 4; c++)
            *(float4*)(dst + 4*c) = make_float4(lo2(pv[2*c]), hi2(pv[2*c]),
                                                lo2(pv[2*c+1]), hi2(pv[2*c+1]));

        if (pass == 0) {
            // ---- Alignments: full columns (zeros off-band), coalesced 128B stores ----
            #pragma unroll 1
            for (int j = warp; j < N_; j += 8) {
                int jj = j - prev;
                float val = (jj >= 0 && jj < WIN_) ? prT[jj*PST + lane] : 0.f;
                out_align[((size_t)b*N_ + j)*T_ + t0 + lane] = val;
            }
            // ---- result[...,256:512] = Q ----
            #pragma unroll
            for (int i = 0; i < 8; i++) {
                int idx = tid + NTHREADS * i;
                int t = idx >> 6, c = idx & 63;
                float4 q = ((const float4*)Qb)[idx];
                ((float4*)out_res)[((size_t)b*T_ + t0 + t)*128 + 64 + c] = q;
            }
            __syncthreads();
            load_half(kbuf, Vw, 1, tid);
            __syncthreads();
        }
    }
}

extern "C" void kernel_launch(void* const* d_in, const int* in_sizes, int n_in,
                              void* d_out, int out_size)
{
    const float* Q    = (const float*)d_in[0];
    const float* K    = (const float*)d_in[1];
    const float* V    = (const float*)d_in[2];
    const int*   prev = (const int*)d_in[3];

    float* out       = (float*)d_out;
    float* out_res   = out;                                   // B*T*2D
    float* out_align = out + (size_t)B_*T_*2*D_;              // B*N*T
    float* out_max   = out_align + (size_t)B_*N_*T_;          // B*T

    cudaFuncSetAttribute(attn_main, cudaFuncAttributeMaxDynamicSharedMemorySize, SMEM_BYTES);
    dim3 grid(T_/TT_, B_);
    attn_main<<<grid, NTHREADS, SMEM_BYTES>>>(Q, K, V, prev, out_res, out_align, out_max);
}

// round 5
// speedup vs baseline: 1.4385x; 1.4385x over previous
#include <cuda_runtime.h>
#include <cstdint>

#define B_    32
#define T_    1024
#define N_    1024
#define D_    256
#define WIN_  100
#define TT_   64           // query-tile per block
#define NTHREADS 512

#define KST 132            // k/v buffer row stride (floats)
#define QROW 260           // qsT row stride (floats)
#define PST 65             // prT row stride (floats)

#define KBUF_F (100*KST)                       // 13200 per buffer
#define QST_F  (64*QROW)                       // 16640
#define PRT_F  (128*PST)                       // 8320
#define SMEM_FLOATS (2*KBUF_F + QST_F + PRT_F) // 51360
#define SMEM_BYTES  (SMEM_FLOATS * 4)          // 205440 B (fits 227KB, 1 CTA/SM)

typedef unsigned long long ull;

__device__ __forceinline__ void fma2(ull& acc, ull a, ull b) {
    asm("fma.rn.f32x2 %0, %1, %2, %0;" : "+l"(acc) : "l"(a), "l"(b));
}
__device__ __forceinline__ ull pack2(float lo, float hi) {
    ull r; asm("mov.b64 %0, {%1, %2};" : "=l"(r) : "f"(lo), "f"(hi)); return r;
}
__device__ __forceinline__ float lo2(ull v) {
    float a, b; asm("mov.b64 {%0, %1}, %2;" : "=f"(a), "=f"(b) : "l"(v)); return a;
}
__device__ __forceinline__ float hi2(ull v) {
    float a, b; asm("mov.b64 {%0, %1}, %2;" : "=f"(a), "=f"(b) : "l"(v)); return b;
}

// load 100 rows x 128 floats (d-half h) of row-major [N][256] window into dst[j*KST + d']
__device__ __forceinline__ void load_half(float* dst, const float* src, int h, int tid) {
    #pragma unroll
    for (int i = 0; i < 7; i++) {
        int idx = tid + NTHREADS * i;            // over 100*32 float4
        if (idx < 100*32) {
            int j = idx >> 5, c = idx & 31;
            float4 v = *(const float4*)(src + (size_t)j*D_ + 128*h + 4*c);
            *(float4*)(dst + j*KST + 4*c) = v;
        }
    }
}

__global__ __launch_bounds__(NTHREADS, 1)
void attn_main(const float* __restrict__ Q, const float* __restrict__ K,
               const float* __restrict__ V, const int* __restrict__ prev_arr,
               float* __restrict__ out_res, float* __restrict__ out_align,
               float* __restrict__ out_max)
{
    extern __shared__ float sm[];
    float* kbuf0 = sm;                     // [100][KST]  K half0, later V half0
    float* kbuf1 = sm + KBUF_F;            // [100][KST]  K half1, later V half1
    float* qsT   = sm + 2*KBUF_F;          // [64 d4][t*4+c]
    float* prT   = qsT + QST_F;            // [128 j][PST]

    const int b    = blockIdx.y;
    const int t0   = blockIdx.x * TT_;
    const int tid  = threadIdx.x;
    const int warp = tid >> 5;             // 0..15
    const int lane = tid & 31;
    const int prev = prev_arr[b];

    const float* Qb = Q + ((size_t)b*T_ + t0) * D_;
    const float* Kw = K + ((size_t)b*N_ + prev) * D_;
    const float* Vw = V + ((size_t)b*N_ + prev) * D_;

    // ---- Load Q tile into qsT AND write the out_res Q-half from the same regs ----
    #pragma unroll
    for (int i = 0; i < 8; i++) {
        int idx = tid + NTHREADS * i;            // 64*64 float4
        int t = idx >> 6, c = idx & 63;
        float4 q = ((const float4*)Qb)[idx];
        *(float4*)(qsT + c*QROW + t*4) = q;
        ((float4*)out_res)[((size_t)b*T_ + t0 + t)*128 + 64 + c] = q;
    }
    // ---- Both K halves up front (double buffer) ----
    load_half(kbuf0, Kw, 0, tid);
    load_half(kbuf1, Kw, 1, tid);
    __syncthreads();

    // ================= QK: warp owns j in [8w,8w+8), lane owns t={lane,lane+32} =====
    const int jw = warp * 8;
    ull acc2[8][2];
    #pragma unroll
    for (int i = 0; i < 8; i++) { acc2[i][0] = 0ull; acc2[i][1] = 0ull; }

    #pragma unroll 1
    for (int pass = 0; pass < 2; pass++) {
        const float* kb = pass ? kbuf1 : kbuf0;
        #pragma unroll 2
        for (int d4 = 0; d4 < 32; d4++) {
            const float* qr = qsT + (32*pass + d4)*QROW;
            ulonglong2 qa = *(const ulonglong2*)(qr + 4*lane);         // t = lane
            ulonglong2 qb = *(const ulonglong2*)(qr + 128 + 4*lane);   // t = lane+32
            #pragma unroll
            for (int i = 0; i < 8; i++) {
                ulonglong2 k2 = *(const ulonglong2*)(kb + (jw + i)*KST + 4*d4);
                fma2(acc2[i][0], qa.x, k2.x);
                fma2(acc2[i][0], qa.y, k2.y);
                fma2(acc2[i][1], qb.x, k2.x);
                fma2(acc2[i][1], qb.y, k2.y);
            }
        }
    }
    const float scale = 0.0625f;
    #pragma unroll
    for (int i = 0; i < 8; i++) {
        prT[(jw + i)*PST + lane]      = (lo2(acc2[i][0]) + hi2(acc2[i][0])) * scale;
        prT[(jw + i)*PST + 32 + lane] = (lo2(acc2[i][1]) + hi2(acc2[i][1])) * scale;
    }
    __syncthreads();

    // ---- Issue BOTH V half loads now; LDG latency hides under softmax ----
    load_half(kbuf0, Vw, 0, tid);
    load_half(kbuf1, Vw, 1, tid);

    // ================= Softmax + argmax: warp owns rows t in [4w,4w+4) ==============
    const int trow = warp * 4;
    #pragma unroll
    for (int tt = 0; tt < 4; tt++) {
        int t = trow + tt;
        float v_[4];
        #pragma unroll
        for (int i = 0; i < 4; i++) v_[i] = prT[(lane + 32*i)*PST + t];   // conflict-free

        float mx = -3.4e38f;
        #pragma unroll
        for (int i = 0; i < 4; i++)
            if (lane + 32*i < WIN_) mx = fmaxf(mx, v_[i]);
        #pragma unroll
        for (int off = 16; off; off >>= 1)
            mx = fmaxf(mx, __shfl_xor_sync(0xffffffffu, mx, off));

        float e_[4]; float s = 0.f;
        #pragma unroll
        for (int i = 0; i < 4; i++) {
            e_[i] = (lane + 32*i < WIN_) ? __expf(v_[i] - mx) : 0.f;
            s += e_[i];
        }
        #pragma unroll
        for (int off = 16; off; off >>= 1)
            s += __shfl_xor_sync(0xffffffffu, s, off);
        float inv = 1.f / s;

        float pr[4];
        #pragma unroll
        for (int i = 0; i < 4; i++) pr[i] = e_[i] * inv;

        // first-occurrence argmax over final probs (jnp.argmax tie rule)
        float bm = -1.f; int bi = N_;
        #pragma unroll
        for (int i = 0; i < 4; i++)
            if (pr[i] > bm) { bm = pr[i]; bi = lane + 32*i; }
        #pragma unroll
        for (int off = 16; off; off >>= 1) {
            float om = __shfl_xor_sync(0xffffffffu, bm, off);
            int   oi = __shfl_xor_sync(0xffffffffu, bi, off);
            if (om > bm || (om == bm && oi < bi)) { bm = om; bi = oi; }
        }
        if (lane == 0)
            out_max[(size_t)b*T_ + t0 + t] = (float)(prev + bi);

        #pragma unroll
        for (int i = 0; i < 4; i++) prT[(lane + 32*i)*PST + t] = pr[i];
    }
    __syncthreads();   // probs final, both V halves resident

    // ---- Alignments: full columns (zeros off-band), coalesced 128B stores ----
    #pragma unroll 1
    for (int j = warp; j < N_; j += 16) {
        int jj = j - prev;
        bool inb = (jj >= 0 && jj < WIN_);
        float v0 = inb ? prT[jj*PST + lane]      : 0.f;
        float v1 = inb ? prT[jj*PST + 32 + lane] : 0.f;
        float* ar = out_align + ((size_t)b*N_ + j)*T_ + t0;
        ar[lane]      = v0;
        ar[32 + lane] = v1;
    }

    // ================= PV fused: warp owns global d in [16w,16w+16) ================
    {
        const float* vb = (warp < 8) ? kbuf0 : kbuf1;
        const int dv = (warp & 7) * 16;
        ull pv[8][2];
        #pragma unroll
        for (int i = 0; i < 8; i++) { pv[i][0] = 0ull; pv[i][1] = 0ull; }

        #pragma unroll 2
        for (int j = 0; j < WIN_; j++) {
            float p0 = prT[j*PST + lane];
            float p1 = prT[j*PST + 32 + lane];
            ull pp0 = pack2(p0, p0);
            ull pp1 = pack2(p1, p1);
            const float* vr = vb + j*KST + dv;
            ulonglong2 v0 = *(const ulonglong2*)(vr);
            ulonglong2 v1 = *(const ulonglong2*)(vr + 4);
            ulonglong2 v2 = *(const ulonglong2*)(vr + 8);
            ulonglong2 v3 = *(const ulonglong2*)(vr + 12);
            fma2(pv[0][0], pp0, v0.x); fma2(pv[1][0], pp0, v0.y);
            fma2(pv[2][0], pp0, v1.x); fma2(pv[3][0], pp0, v1.y);
            fma2(pv[4][0], pp0, v2.x); fma2(pv[5][0], pp0, v2.y);
            fma2(pv[6][0], pp0, v3.x); fma2(pv[7][0], pp0, v3.y);
            fma2(pv[0][1], pp1, v0.x); fma2(pv[1][1], pp1, v0.y);
            fma2(pv[2][1], pp1, v1.x); fma2(pv[3][1], pp1, v1.y);
            fma2(pv[4][1], pp1, v2.x); fma2(pv[5][1], pp1, v2.y);
            fma2(pv[6][1], pp1, v3.x); fma2(pv[7][1], pp1, v3.y);
        }
        #pragma unroll
        for (int tp = 0; tp < 2; tp++) {
            int t = lane + 32*tp;
            float* dst = out_res + ((size_t)b*T_ + t0 + t)*(2*D_) + warp*16;
            #pragma unroll
            for (int c = 0; c < 4; c++)
                *(float4*)(dst + 4*c) = make_float4(lo2(pv[2*c][tp]),   hi2(pv[2*c][tp]),
                                                    lo2(pv[2*c+1][tp]), hi2(pv[2*c+1][tp]));
        }
    }
}

extern "C" void kernel_launch(void* const* d_in, const int* in_sizes, int n_in,
                              void* d_out, int out_size)
{
    const float* Q    = (const float*)d_in[0];
    const float* K    = (const float*)d_in[1];
    const float* V    = (const float*)d_in[2];
    const int*   prev = (const int*)d_in[3];

    float* out       = (float*)d_out;
    float* out_res   = out;                                   // B*T*2D
    float* out_align = out + (size_t)B_*T_*2*D_;              // B*N*T
    float* out_max   = out_align + (size_t)B_*N_*T_;          // B*T

    cudaFuncSetAttribute(attn_main, cudaFuncAttributeMaxDynamicSharedMemorySize, SMEM_BYTES);
    dim3 grid(T_/TT_, B_);
    attn_main<<<grid, NTHREADS, SMEM_BYTES>>>(Q, K, V, prev, out_res, out_align, out_max);
}

// round 7
// speedup vs baseline: 1.4988x; 1.0419x over previous
#include <cuda_runtime.h>
#include <cuda_bf16.h>
#include <cstdint>

#define B_    32
#define T_    1024
#define N_    1024
#define D_    256
#define WIN_  100
#define TT_   64
#define NTHREADS 512

#define PST 65              // prT row stride (floats)
#define VST 260             // V buffer row stride (floats)

#define KROW 264            // bf16 row stride (528 B, conflict-free for ldmatrix)
#define KRB  (KROW*2)       // 528 bytes

// smem byte offsets
#define OFF_KH 0
#define OFF_KL (OFF_KH + 128*KRB)        //  67584
#define OFF_QH (OFF_KL + 128*KRB)        // 135168
#define OFF_QL (OFF_QH + 64*KRB)         // 168960
#define SMEM_BYTES (OFF_QL + 64*KRB)     // 202752
// aliases (dead after QK mma)
#define OFF_PRT 0                        // [128][PST] f32
#define OFF_VB  33280                    // [100][VST] f32 (ends 137280)

typedef unsigned long long ull;

__device__ __forceinline__ void fma2(ull& acc, ull a, ull b) {
    asm("fma.rn.f32x2 %0, %1, %2, %0;" : "+l"(acc) : "l"(a), "l"(b));
}
__device__ __forceinline__ ull pack2(float lo, float hi) {
    ull r; asm("mov.b64 %0, {%1, %2};" : "=l"(r) : "f"(lo), "f"(hi)); return r;
}
__device__ __forceinline__ float lo2(ull v) {
    float a, b; asm("mov.b64 {%0, %1}, %2;" : "=f"(a), "=f"(b) : "l"(v)); return a;
}
__device__ __forceinline__ float hi2(ull v) {
    float a, b; asm("mov.b64 {%0, %1}, %2;" : "=f"(a), "=f"(b) : "l"(v)); return b;
}
__device__ __forceinline__ uint32_t smem_u32(const void* p) {
    uint32_t a;
    asm("{ .reg .u64 t; cvta.to.shared.u64 t, %1; cvt.u32.u64 %0, t; }" : "=r"(a) : "l"(p));
    return a;
}
__device__ __forceinline__ void ldsm4(uint32_t& r0, uint32_t& r1, uint32_t& r2, uint32_t& r3,
                                      uint32_t addr) {
    asm volatile("ldmatrix.sync.aligned.m8n8.x4.shared.b16 {%0,%1,%2,%3}, [%4];"
                 : "=r"(r0), "=r"(r1), "=r"(r2), "=r"(r3) : "r"(addr));
}
__device__ __forceinline__ void mma16816(float* d, const uint32_t* a, uint32_t b0, uint32_t b1) {
    asm volatile("mma.sync.aligned.m16n8k16.row.col.f32.bf16.bf16.f32 "
                 "{%0,%1,%2,%3}, {%4,%5,%6,%7}, {%8,%9}, {%0,%1,%2,%3};"
                 : "+f"(d[0]), "+f"(d[1]), "+f"(d[2]), "+f"(d[3])
                 : "r"(a[0]), "r"(a[1]), "r"(a[2]), "r"(a[3]), "r"(b0), "r"(b1));
}
// split 8 fp32 -> bf16 hi/lo packed pairs
__device__ __forceinline__ void split8(const float* f, uint32_t* h4, uint32_t* l4) {
    #pragma unroll
    for (int i = 0; i < 4; i++) {
        __nv_bfloat16 h0 = __float2bfloat16(f[2*i]), h1 = __float2bfloat16(f[2*i+1]);
        float r0 = f[2*i]   - __bfloat162float(h0);
        float r1 = f[2*i+1] - __bfloat162float(h1);
        __nv_bfloat16 l0 = __float2bfloat16(r0), l1 = __float2bfloat16(r1);
        h4[i] = (uint32_t)__bfloat16_as_ushort(h0) | ((uint32_t)__bfloat16_as_ushort(h1) << 16);
        l4[i] = (uint32_t)__bfloat16_as_ushort(l0) | ((uint32_t)__bfloat16_as_ushort(l1) << 16);
    }
}

__global__ __launch_bounds__(NTHREADS, 1)
void attn_main(const float* __restrict__ Q, const float* __restrict__ K,
               const float* __restrict__ V, const int* __restrict__ prev_arr,
               float* __restrict__ out_res, float* __restrict__ out_align,
               float* __restrict__ out_max)
{
    extern __shared__ __align__(128) char sm[];
    const uint32_t smb = smem_u32(sm);
    float* prT = (float*)(sm + OFF_PRT);
    float* vb  = (float*)(sm + OFF_VB);

    const int b    = blockIdx.y;
    const int t0   = blockIdx.x * TT_;
    const int tid  = threadIdx.x;
    const int warp = tid >> 5;
    const int lane = tid & 31;
    const int prev = prev_arr[b];

    const float* Qb = Q + ((size_t)b*T_ + t0) * D_;
    const float* Kw = K + ((size_t)b*N_ + prev) * D_;
    const float* Vw = V + ((size_t)b*N_ + prev) * D_;

    // ---- Load Q (64x256): write out_res Q-half + split-store Qh/Ql ----
    #pragma unroll
    for (int it = 0; it < 4; it++) {
        int idx = tid + NTHREADS * it;        // t = idx/32, 8-float chunk g = idx%32
        int t = idx >> 5, g = idx & 31;
        const float* src = Qb + (size_t)t * D_ + 8*g;
        float4 a = *(const float4*)(src);
        float4 c = *(const float4*)(src + 4);
        float f[8] = {a.x,a.y,a.z,a.w,c.x,c.y,c.z,c.w};
        float* qdst = out_res + ((size_t)b*T_ + t0 + t) * (2*D_) + 256 + 8*g;
        *(float4*)(qdst)     = a;
        *(float4*)(qdst + 4) = c;
        uint32_t h4[4], l4[4];
        split8(f, h4, l4);
        uint32_t off = (uint32_t)(t*KRB + 16*g);
        *(uint4*)(sm + OFF_QH + off) = make_uint4(h4[0],h4[1],h4[2],h4[3]);
        *(uint4*)(sm + OFF_QL + off) = make_uint4(l4[0],l4[1],l4[2],l4[3]);
    }
    // ---- Load K (rows 0..99, zero-pad to 128): split-store Kh/Kl ----
    #pragma unroll
    for (int it = 0; it < 8; it++) {
        int idx = tid + NTHREADS * it;
        int j = idx >> 5, g = idx & 31;
        float f[8] = {0,0,0,0,0,0,0,0};
        if (j < WIN_) {
            const float* src = Kw + (size_t)j * D_ + 8*g;
            float4 a = *(const float4*)(src);
            float4 c = *(const float4*)(src + 4);
            f[0]=a.x; f[1]=a.y; f[2]=a.z; f[3]=a.w; f[4]=c.x; f[5]=c.y; f[6]=c.z; f[7]=c.w;
        }
        uint32_t h4[4], l4[4];
        split8(f, h4, l4);
        uint32_t off = (uint32_t)(j*KRB + 16*g);
        *(uint4*)(sm + OFF_KH + off) = make_uint4(h4[0],h4[1],h4[2],h4[3]);
        *(uint4*)(sm + OFF_KL + off) = make_uint4(l4[0],l4[1],l4[2],l4[3]);
    }
    __syncthreads();

    // ============ QK via HMMA: S[64t x 128j]; warp: m-tile=w%4, n-tiles 4*(w/4).. ====
    const int mi  = warp & 3;
    const int nj0 = (warp >> 2) * 32;

    float dacc[4][4];
    #pragma unroll
    for (int nt = 0; nt < 4; nt++)
        #pragma unroll
        for (int i = 0; i < 4; i++) dacc[nt][i] = 0.f;

    // lane addresses
    const uint32_t aOff = (uint32_t)((mi*16 + (lane & 15))*KRB + ((lane >> 4) & 1)*16);
    const int nB  = nj0 + ((lane >> 4) & 1)*8 + (lane & 7);
    const uint32_t bOff = (uint32_t)(nB*KRB + ((lane >> 3) & 1)*16);
    const uint32_t aQh = smb + OFF_QH + aOff;
    const uint32_t aQl = smb + OFF_QL + aOff;
    const uint32_t bKh0 = smb + OFF_KH + bOff;
    const uint32_t bKl0 = smb + OFF_KL + bOff;

    #pragma unroll 1
    for (int term = 0; term < 3; term++) {
        uint32_t aB  = (term == 2) ? aQl : aQh;
        uint32_t bB0 = (term == 1) ? bKl0 : bKh0;
        uint32_t bB1 = bB0 + 16*KRB;
        #pragma unroll 4
        for (int ks = 0; ks < 16; ks++) {
            uint32_t a[4], b0[4], b1[4];
            ldsm4(a[0], a[1], a[2], a[3], aB + ks*32);
            ldsm4(b0[0], b0[1], b0[2], b0[3], bB0 + ks*32);
            ldsm4(b1[0], b1[1], b1[2], b1[3], bB1 + ks*32);
            mma16816(dacc[0], a, b0[0], b0[1]);
            mma16816(dacc[1], a, b0[2], b0[3]);
            mma16816(dacc[2], a, b1[0], b1[1]);
            mma16816(dacc[3], a, b1[2], b1[3]);
        }
    }
    __syncthreads();   // all reads of Kh/Kl/Qh/Ql complete -> safe to alias

    // ---- Store scores transposed into prT[j][t], scaled by 1/16 ----
    {
        const float s = 0.0625f;
        int tb = mi*16 + (lane >> 2);
        int jb = nj0 + (lane & 3)*2;
        #pragma unroll
        for (int nt = 0; nt < 4; nt++) {
            int j = jb + nt*8;
            prT[(j  )*PST + tb    ] = dacc[nt][0] * s;
            prT[(j+1)*PST + tb    ] = dacc[nt][1] * s;
            prT[(j  )*PST + tb + 8] = dacc[nt][2] * s;
            prT[(j+1)*PST + tb + 8] = dacc[nt][3] * s;
        }
    }
    // ---- Copy V window into vb ----
    #pragma unroll 1
    for (int idx = tid; idx < 6400; idx += NTHREADS) {
        int j = idx >> 6, c = idx & 63;
        float4 v = *(const float4*)(Vw + (size_t)j*D_ + 4*c);
        *(float4*)(vb + j*VST + 4*c) = v;
    }
    __syncthreads();

    // ================= Softmax + argmax: warp owns rows t in [4w,4w+4) ==============
    const int trow = warp * 4;
    #pragma unroll
    for (int tt = 0; tt < 4; tt++) {
        int t = trow + tt;
        float v_[4];
        #pragma unroll
        for (int i = 0; i < 4; i++) v_[i] = prT[(lane + 32*i)*PST + t];

        float mx = -3.4e38f;
        #pragma unroll
        for (int i = 0; i < 4; i++)
            if (lane + 32*i < WIN_) mx = fmaxf(mx, v_[i]);
        #pragma unroll
        for (int off = 16; off; off >>= 1)
            mx = fmaxf(mx, __shfl_xor_sync(0xffffffffu, mx, off));

        float e_[4]; float s = 0.f;
        #pragma unroll
        for (int i = 0; i < 4; i++) {
            e_[i] = (lane + 32*i < WIN_) ? __expf(v_[i] - mx) : 0.f;
            s += e_[i];
        }
        #pragma unroll
        for (int off = 16; off; off >>= 1)
            s += __shfl_xor_sync(0xffffffffu, s, off);
        float inv = 1.f / s;

        float pr[4];
        #pragma unroll
        for (int i = 0; i < 4; i++) pr[i] = e_[i] * inv;

        // first-occurrence argmax over final probs (jnp.argmax tie rule)
        float bm = -1.f; int bi = N_;
        #pragma unroll
        for (int i = 0; i < 4; i++)
            if (pr[i] > bm) { bm = pr[i]; bi = lane + 32*i; }
        #pragma unroll
        for (int off = 16; off; off >>= 1) {
            float om = __shfl_xor_sync(0xffffffffu, bm, off);
            int   oi = __shfl_xor_sync(0xffffffffu, bi, off);
            if (om > bm || (om == bm && oi < bi)) { bm = om; bi = oi; }
        }
        if (lane == 0)
            out_max[(size_t)b*T_ + t0 + t] = (float)(prev + bi);

        #pragma unroll
        for (int i = 0; i < 4; i++) prT[(lane + 32*i)*PST + t] = pr[i];
    }
    __syncthreads();

    // ---- Alignments: full columns (zeros off-band), coalesced ----
    #pragma unroll 1
    for (int j = warp; j < N_; j += 16) {
        int jj = j - prev;
        bool inb = (jj >= 0 && jj < WIN_);
        float v0 = inb ? prT[jj*PST + lane]      : 0.f;
        float v1 = inb ? prT[jj*PST + 32 + lane] : 0.f;
        float* ar = out_align + ((size_t)b*N_ + j)*T_ + t0;
        ar[lane]      = v0;
        ar[32 + lane] = v1;
    }

    // ================= PV scalar fused: warp owns d in [16w,16w+16) =================
    {
        const int dv = warp * 16;
        ull pv[8][2];
        #pragma unroll
        for (int i = 0; i < 8; i++) { pv[i][0] = 0ull; pv[i][1] = 0ull; }

        #pragma unroll 2
        for (int j = 0; j < WIN_; j++) {
            float p0 = prT[j*PST + lane];
            float p1 = prT[j*PST + 32 + lane];
            ull pp0 = pack2(p0, p0);
            ull pp1 = pack2(p1, p1);
            const float* vr = vb + j*VST + dv;
            ulonglong2 v0 = *(const ulonglong2*)(vr);
            ulonglong2 v1 = *(const ulonglong2*)(vr + 4);
            ulonglong2 v2 = *(const ulonglong2*)(vr + 8);
            ulonglong2 v3 = *(const ulonglong2*)(vr + 12);
            fma2(pv[0][0], pp0, v0.x); fma2(pv[1][0], pp0, v0.y);
            fma2(pv[2][0], pp0, v1.x); fma2(pv[3][0], pp0, v1.y);
            fma2(pv[4][0], pp0, v2.x); fma2(pv[5][0], pp0, v2.y);
            fma2(pv[6][0], pp0, v3.x); fma2(pv[7][0], pp0, v3.y);
            fma2(pv[0][1], pp1, v0.x); fma2(pv[1][1], pp1, v0.y);
            fma2(pv[2][1], pp1, v1.x); fma2(pv[3][1], pp1, v1.y);
            fma2(pv[4][1], pp1, v2.x); fma2(pv[5][1], pp1, v2.y);
            fma2(pv[6][1], pp1, v3.x); fma2(pv[7][1], pp1, v3.y);
        }
        #pragma unroll
        for (int tp = 0; tp < 2; tp++) {
            int t = lane + 32*tp;
            float* dst = out_res + ((size_t)b*T_ + t0 + t)*(2*D_) + dv;
            #pragma unroll
            for (int c = 0; c < 4; c++)
                *(float4*)(dst + 4*c) = make_float4(lo2(pv[2*c][tp]),   hi2(pv[2*c][tp]),
                                                    lo2(pv[2*c+1][tp]), hi2(pv[2*c+1][tp]));
        }
    }
}

extern "C" void kernel_launch(void* const* d_in, const int* in_sizes, int n_in,
                              void* d_out, int out_size)
{
    const float* Q    = (const float*)d_in[0];
    const float* K    = (const float*)d_in[1];
    const float* V    = (const float*)d_in[2];
    const int*   prev = (const int*)d_in[3];

    float* out       = (float*)d_out;
    float* out_res   = out;                                   // B*T*2D
    float* out_align = out + (size_t)B_*T_*2*D_;              // B*N*T
    float* out_max   = out_align + (size_t)B_*N_*T_;          // B*T

    cudaFuncSetAttribute(attn_main, cudaFuncAttributeMaxDynamicSharedMemorySize, SMEM_BYTES);
    dim3 grid(T_/TT_, B_);
    attn_main<<<grid, NTHREADS, SMEM_BYTES>>>(Q, K, V, prev, out_res, out_align, out_max);
}